// round 6
// baseline (speedup 1.0000x reference)
#include <cuda_runtime.h>
#include <cstdint>

#define T_STEPS 300
#define E_DIM   300
#define H_DIM   512
#define G_DIM   2048   // 4*H
#define N_EXP   13
#define V_SIZE  400000
#define NCTA    128    // recurrent CTAs; 4 hidden units each
#define ROWS_PER_BLK 32
#define GATE_BLOCKS (N_EXP * (G_DIM / ROWS_PER_BLK))   // 832
#define SNAN_BITS 0x7fc00000

// Scratch (device globals: no allocation allowed)
__device__ float g_gates[T_STEPS * G_DIM];                      // input gates (+biases)
__device__ __align__(16) float g_h[(T_STEPS + 1) * H_DIM];      // step-indexed hidden states

// ---------------------------------------------------------------------------
// Volatile global access helpers (compiler cannot hoist/elide/fold these)
// ---------------------------------------------------------------------------
__device__ __forceinline__ float2 ld_vol_f2(const float2* p) {
    float2 v;
    asm volatile("ld.volatile.global.v2.f32 {%0,%1}, [%2];"
                 : "=f"(v.x), "=f"(v.y) : "l"(p));
    return v;
}
__device__ __forceinline__ void st_vol_f(float* p, float v) {
    asm volatile("st.volatile.global.f32 [%0], %1;" :: "l"(p), "f"(v));
}
__device__ __forceinline__ bool is_snan(float v) { return __float_as_int(v) == SNAN_BITS; }

// ---------------------------------------------------------------------------
// Kernel 1: re-init h ladder each replay. g_h[0]=h0, rest sentinel.
// ---------------------------------------------------------------------------
__global__ void init_kernel(const float* __restrict__ h0) {
    int idx = blockIdx.x * blockDim.x + threadIdx.x;
    if (idx < (T_STEPS + 1) * H_DIM)
        g_h[idx] = (idx < H_DIM) ? h0[idx] : __int_as_float(SNAN_BITS);
}

// ---------------------------------------------------------------------------
// x-buffer probe: reference declares int64 but JAX w/o x64 yields int32.
// If truly int64, every odd 32-bit word is 0 (ids in [0, 4e5)).
// ---------------------------------------------------------------------------
__device__ __forceinline__ bool probe_is_i64(const int* __restrict__ x32) {
    bool all_zero = true;
    #pragma unroll
    for (int i = 1; i < 64; i += 2) all_zero &= (x32[i] == 0);
    return all_zero;
}
__device__ __forceinline__ int load_token(const int* __restrict__ x32, int t, bool i64) {
    int v = i64 ? x32[2 * t] : x32[t];
    return (v < 0) ? 0 : (v >= V_SIZE ? V_SIZE - 1 : v);
}

// ---------------------------------------------------------------------------
// Kernel 2: input gates. Block = (expert, 32-row chunk). W_ih chunk in SMEM
// once; loop timesteps routed to this expert. Stream-ordered before lstm.
// gates[t][row] = dot(emb[x[t]], W_ih[e][row]) + b_ih[e][row] + b_hh[e][row]
// ---------------------------------------------------------------------------
__global__ void __launch_bounds__(256) gates_kernel(
    const int* __restrict__ x32, const int* __restrict__ tags,
    const float* __restrict__ emb, const float* __restrict__ W_ih,
    const float* __restrict__ b_ih, const float* __restrict__ b_hh)
{
    __shared__ float sw[ROWS_PER_BLK * E_DIM];   // 37.5 KB
    __shared__ float sx[E_DIM];
    __shared__ float sb[ROWS_PER_BLK];
    __shared__ int   stags[T_STEPS];
    __shared__ int   s_i64;

    const int e     = blockIdx.x / (G_DIM / ROWS_PER_BLK);
    const int chunk = blockIdx.x % (G_DIM / ROWS_PER_BLK);
    const int row0  = chunk * ROWS_PER_BLK;
    const int tid   = threadIdx.x;

    const float* wsrc = W_ih + ((size_t)e * G_DIM + row0) * E_DIM;
    for (int i = tid; i < ROWS_PER_BLK * E_DIM; i += 256) sw[i] = wsrc[i];
    if (tid < ROWS_PER_BLK)
        sb[tid] = b_ih[e * G_DIM + row0 + tid] + b_hh[e * G_DIM + row0 + tid];
    for (int i = tid; i < T_STEPS; i += 256) stags[i] = tags[i];
    if (tid == 0) s_i64 = probe_is_i64(x32) ? 1 : 0;
    __syncthreads();

    const bool i64  = (s_i64 != 0);
    const int row   = tid >> 3;   // 0..31
    const int lane8 = tid & 7;

    for (int t = 0; t < T_STEPS; t++) {
        if (stags[t] != e) continue;                 // uniform branch (smem)
        const float* xe = emb + (size_t)load_token(x32, t, i64) * E_DIM;
        for (int i = tid; i < E_DIM; i += 256) sx[i] = xe[i];
        __syncthreads();
        float acc = 0.f;
        for (int k = lane8; k < E_DIM; k += 8)
            acc += sw[row * E_DIM + k] * sx[k];
        #pragma unroll
        for (int off = 4; off; off >>= 1)
            acc += __shfl_down_sync(0xffffffffu, acc, off, 8);
        if (lane8 == 0)
            g_gates[t * G_DIM + row0 + row] = acc + sb[row];
        __syncthreads();
    }
}

// ---------------------------------------------------------------------------
// Kernel 3: persistent recurrent LSTM. 128 CTAs x 256 threads.
// CTA b owns hidden units [4b, 4b+4); 16 gate rows per step.
// Sync: sentinel polling on step-indexed g_h; own units bypass global poll
// (warp 0 deposits them straight into smem). Block 0 also computes the FC out.
// ---------------------------------------------------------------------------
__global__ void __launch_bounds__(256, 1) lstm_kernel(
    const int* __restrict__ tags, const float* __restrict__ W_hh,
    const float* __restrict__ c0,
    const float* __restrict__ fc_w, const float* __restrict__ fc_b,
    float* __restrict__ d_out, int out_size)
{
    __shared__ __align__(16) float sh[H_DIM];   // h[s] staged for dot products
    __shared__ float ssum[16];                  // per-row dot sums
    __shared__ int   stags[T_STEPS];

    const int tid    = threadIdx.x;
    const int base   = blockIdx.x * 4;           // first hidden unit owned
    const int rid    = tid >> 4;                 // 0..15: gate row id
    const int lane16 = tid & 15;
    const int g      = rid >> 2;                 // gate: 0=i 1=f 2=g 3=o
    const int ul     = rid & 3;                  // unit within CTA
    const int row    = g * H_DIM + base + ul;    // global gate row
    // threads that would poll this CTA's own h units (skip the global trip)
    const bool self_poll = (tid >> 1) == blockIdx.x;

    for (int i = tid; i < T_STEPS; i += 256) stags[i] = tags[i];
    float cval = 0.f, hval = 0.f;
    if (tid < 4) cval = c0[base + tid];
    __syncthreads();

    // Preload step-0 weights: thread handles k = lane16*4 + 64*m, m=0..7
    float4 wc[8], wn[8];
    {
        const float4* p = (const float4*)(W_hh + ((size_t)stags[0] * G_DIM + row) * H_DIM + lane16 * 4);
        #pragma unroll
        for (int m = 0; m < 8; m++) wc[m] = __ldg(&p[m * 16]);
    }
    // Seed smem with own units of h[0] (they're never globally polled)
    if (tid < 4) sh[base + tid] = g_h[base + tid];

    const float2* ghp = (const float2*)g_h;

    for (int s = 0; s < T_STEPS; s++) {
        // 1. Prefetch next step's weights (tags known upfront -> hides L2 latency)
        {
            int sn = (s + 1 < T_STEPS) ? s + 1 : s;
            const float4* p = (const float4*)(W_hh + ((size_t)stags[sn] * G_DIM + row) * H_DIM + lane16 * 4);
            #pragma unroll
            for (int m = 0; m < 8; m++) wn[m] = __ldg(&p[m * 16]);
        }
        // 2. Prefetch this step's input gate for the nonlinearity lane (tid<16);
        //    same thread consumes it later -> stays in a register, no smem.
        float gin = 0.f;
        if (tid < 16)
            gin = __ldg(&g_gates[s * G_DIM + (tid >> 2) * H_DIM + base + (tid & 3)]);

        // 3. Poll h[s]: each thread owns 2 floats; sentinel bits = not ready.
        if (!self_poll) {
            float2 hv = ld_vol_f2(&ghp[s * (H_DIM / 2) + tid]);
            while (is_snan(hv.x) || is_snan(hv.y))
                hv = ld_vol_f2(&ghp[s * (H_DIM / 2) + tid]);
            sh[2 * tid]     = hv.x;
            sh[2 * tid + 1] = hv.y;
        }
        __syncthreads();

        // 4. 16-lane dot product, 4 accumulators (short FMA chains)
        const float4* sh4 = (const float4*)sh;
        float a0 = 0.f, a1 = 0.f, a2 = 0.f, a3 = 0.f;
        #pragma unroll
        for (int m = 0; m < 8; m += 4) {
            float4 h0v = sh4[lane16 + (m + 0) * 16];
            float4 h1v = sh4[lane16 + (m + 1) * 16];
            float4 h2v = sh4[lane16 + (m + 2) * 16];
            float4 h3v = sh4[lane16 + (m + 3) * 16];
            a0 += wc[m+0].x * h0v.x + wc[m+0].y * h0v.y + wc[m+0].z * h0v.z + wc[m+0].w * h0v.w;
            a1 += wc[m+1].x * h1v.x + wc[m+1].y * h1v.y + wc[m+1].z * h1v.z + wc[m+1].w * h1v.w;
            a2 += wc[m+2].x * h2v.x + wc[m+2].y * h2v.y + wc[m+2].z * h2v.z + wc[m+2].w * h2v.w;
            a3 += wc[m+3].x * h3v.x + wc[m+3].y * h3v.y + wc[m+3].z * h3v.z + wc[m+3].w * h3v.w;
        }
        float acc = (a0 + a1) + (a2 + a3);
        #pragma unroll
        for (int off = 8; off; off >>= 1)
            acc += __shfl_down_sync(0xffffffffu, acc, off, 16);
        if (lane16 == 0) ssum[rid] = acc;
        __syncthreads();

        // 5. Parallel nonlinearity in warp 0 lanes 0-15 (one MUFU path each),
        //    gather i/f/g/o to lanes 0-3, update c/h, publish h[s+1].
        if (tid < 16) {
            float v = gin + ssum[tid];
            bool isg = ((tid >> 2) == 2);                 // tanh gate
            float e  = __expf(isg ? -2.f * v : -v);
            float val = __fdividef(isg ? 1.f - e : 1.f, 1.f + e);  // tanh or sigmoid
            int u = tid & 3;
            float fv = __shfl_sync(0xffffu, val, u + 4);
            float gv = __shfl_sync(0xffffu, val, u + 8);
            float ov = __shfl_sync(0xffffu, val, u + 12);
            if (tid < 4) {
                cval = fv * cval + val * gv;              // val = i for lanes 0-3
                float e2 = __expf(-2.f * cval);
                hval = ov * __fdividef(1.f - e2, 1.f + e2);
                st_vol_f(&g_h[(s + 1) * H_DIM + base + tid], hval);  // flag for others
                sh[base + tid] = hval;                    // own units: smem direct
            }
        }
        #pragma unroll
        for (int m = 0; m < 8; m++) wc[m] = wn[m];
    }

    // Output layout: [out(1), h(512), c(512)] — h/c only if harness sized it so
    if (tid < 4 && out_size >= 1 + 2 * H_DIM) {
        d_out[1 + base + tid]         = hval;
        d_out[1 + H_DIM + base + tid] = cval;
    }

    // Block 0: out = sigmoid(h_T . fc_w + fc_b)   (fused out_kernel)
    if (blockIdx.x == 0) {
        const float2* hp = (const float2*)(g_h + T_STEPS * H_DIM);
        float2 hv = ld_vol_f2(&hp[tid]);
        while (is_snan(hv.x) || is_snan(hv.y)) hv = ld_vol_f2(&hp[tid]);
        float v = hv.x * __ldg(&fc_w[2 * tid]) + hv.y * __ldg(&fc_w[2 * tid + 1]);
        #pragma unroll
        for (int off = 16; off; off >>= 1) v += __shfl_down_sync(0xffffffffu, v, off);
        if ((tid & 31) == 0) ssum[tid >> 5] = v;
        __syncthreads();
        if (tid < 8) {
            v = ssum[tid];
            #pragma unroll
            for (int off = 4; off; off >>= 1) v += __shfl_down_sync(0xffu, v, off, 8);
            if (tid == 0) d_out[0] = __fdividef(1.f, 1.f + __expf(-(v + fc_b[0])));
        }
    }
}

// ---------------------------------------------------------------------------
// Launch. Input order: x, tags, h0, c0, emb, W_ih, W_hh, b_ih, b_hh, fc_w, fc_b.
// ---------------------------------------------------------------------------
extern "C" void kernel_launch(void* const* d_in, const int* in_sizes, int n_in,
                              void* d_out, int out_size)
{
    const int*   x32  = (const int*)  d_in[0];   // int32 OR int64 (device probe)
    const int*   tags = (const int*)  d_in[1];
    const float* h0   = (const float*)d_in[2];
    const float* c0   = (const float*)d_in[3];
    const float* emb  = (const float*)d_in[4];
    const float* W_ih = (const float*)d_in[5];
    const float* W_hh = (const float*)d_in[6];
    const float* b_ih = (const float*)d_in[7];
    const float* b_hh = (const float*)d_in[8];
    const float* fc_w = (const float*)d_in[9];
    const float* fc_b = (const float*)d_in[10];
    float* out = (float*)d_out;

    init_kernel<<<((T_STEPS + 1) * H_DIM + 511) / 512, 512>>>(h0);
    gates_kernel<<<GATE_BLOCKS, 256>>>(x32, tags, emb, W_ih, b_ih, b_hh);
    lstm_kernel<<<NCTA, 256>>>(tags, W_hh, c0, fc_w, fc_b, out, out_size);
}

// round 7
// speedup vs baseline: 1.1128x; 1.1128x over previous
#include <cuda_runtime.h>
#include <cstdint>

#define T_STEPS 300
#define E_DIM   300
#define H_DIM   512
#define G_DIM   2048   // 4*H
#define N_EXP   13
#define V_SIZE  400000
#define NCTA    128    // recurrent CTAs; 4 hidden units each
#define ROWS_PER_BLK 32
#define GATE_BLOCKS (N_EXP * (G_DIM / ROWS_PER_BLK))   // 832
#define SNAN_BITS 0x7fc00000

// Scratch (device globals: no allocation allowed)
__device__ float g_gates[T_STEPS * G_DIM];                      // input gates (+biases)
__device__ __align__(16) float g_h[(T_STEPS + 1) * H_DIM];      // step-indexed hidden states

// ---------------------------------------------------------------------------
// Volatile global access helpers (compiler cannot hoist/elide/fold these)
// ---------------------------------------------------------------------------
__device__ __forceinline__ float2 ld_vol_f2(const float2* p) {
    float2 v;
    asm volatile("ld.volatile.global.v2.f32 {%0,%1}, [%2];"
                 : "=f"(v.x), "=f"(v.y) : "l"(p));
    return v;
}
__device__ __forceinline__ void st_vol_f(float* p, float v) {
    asm volatile("st.volatile.global.f32 [%0], %1;" :: "l"(p), "f"(v));
}
__device__ __forceinline__ bool is_snan(float v) { return __float_as_int(v) == SNAN_BITS; }

// ---------------------------------------------------------------------------
// Kernel 1: re-init h ladder each replay. g_h[0]=h0, rest sentinel.
// ---------------------------------------------------------------------------
__global__ void init_kernel(const float* __restrict__ h0) {
    int idx = blockIdx.x * blockDim.x + threadIdx.x;
    if (idx < (T_STEPS + 1) * H_DIM)
        g_h[idx] = (idx < H_DIM) ? h0[idx] : __int_as_float(SNAN_BITS);
}

// ---------------------------------------------------------------------------
// x-buffer probe: reference declares int64 but JAX w/o x64 yields int32.
// If truly int64, every odd 32-bit word is 0 (ids in [0, 4e5)).
// ---------------------------------------------------------------------------
__device__ __forceinline__ bool probe_is_i64(const int* __restrict__ x32) {
    bool all_zero = true;
    #pragma unroll
    for (int i = 1; i < 64; i += 2) all_zero &= (x32[i] == 0);
    return all_zero;
}
__device__ __forceinline__ int load_token(const int* __restrict__ x32, int t, bool i64) {
    int v = i64 ? x32[2 * t] : x32[t];
    return (v < 0) ? 0 : (v >= V_SIZE ? V_SIZE - 1 : v);
}

// ---------------------------------------------------------------------------
// Kernel 2: input gates (unchanged from the 848us R4 baseline).
// gates[t][row] = dot(emb[x[t]], W_ih[e][row]) + b_ih[e][row] + b_hh[e][row]
// ---------------------------------------------------------------------------
__global__ void __launch_bounds__(256) gates_kernel(
    const int* __restrict__ x32, const int* __restrict__ tags,
    const float* __restrict__ emb, const float* __restrict__ W_ih,
    const float* __restrict__ b_ih, const float* __restrict__ b_hh)
{
    __shared__ float sw[ROWS_PER_BLK * E_DIM];   // 37.5 KB
    __shared__ float sx[E_DIM];
    __shared__ float sb[ROWS_PER_BLK];
    __shared__ int   stags[T_STEPS];
    __shared__ int   s_i64;

    const int e     = blockIdx.x / (G_DIM / ROWS_PER_BLK);
    const int chunk = blockIdx.x % (G_DIM / ROWS_PER_BLK);
    const int row0  = chunk * ROWS_PER_BLK;
    const int tid   = threadIdx.x;

    const float* wsrc = W_ih + ((size_t)e * G_DIM + row0) * E_DIM;
    for (int i = tid; i < ROWS_PER_BLK * E_DIM; i += 256) sw[i] = wsrc[i];
    if (tid < ROWS_PER_BLK)
        sb[tid] = b_ih[e * G_DIM + row0 + tid] + b_hh[e * G_DIM + row0 + tid];
    for (int i = tid; i < T_STEPS; i += 256) stags[i] = tags[i];
    if (tid == 0) s_i64 = probe_is_i64(x32) ? 1 : 0;
    __syncthreads();

    const bool i64  = (s_i64 != 0);
    const int row   = tid >> 3;   // 0..31
    const int lane8 = tid & 7;

    for (int t = 0; t < T_STEPS; t++) {
        if (stags[t] != e) continue;                 // uniform branch (smem)
        const float* xe = emb + (size_t)load_token(x32, t, i64) * E_DIM;
        for (int i = tid; i < E_DIM; i += 256) sx[i] = xe[i];
        __syncthreads();
        float acc = 0.f;
        for (int k = lane8; k < E_DIM; k += 8)
            acc += sw[row * E_DIM + k] * sx[k];
        #pragma unroll
        for (int off = 4; off; off >>= 1)
            acc += __shfl_down_sync(0xffffffffu, acc, off, 8);
        if (lane8 == 0)
            g_gates[t * G_DIM + row0 + row] = acc + sb[row];
        __syncthreads();
    }
}

// ---------------------------------------------------------------------------
// Kernel 3: persistent recurrent LSTM — R4 structure (all threads poll, sgin
// smem) with (a) pipelined low-period poll loop, (b) fast MUFU nonlinearity
// computed serial-in-lane (ILP, no shfl), (c) fused FC output in block 0.
// ---------------------------------------------------------------------------
__global__ void __launch_bounds__(256, 1) lstm_kernel(
    const int* __restrict__ tags, const float* __restrict__ W_hh,
    const float* __restrict__ c0,
    const float* __restrict__ fc_w, const float* __restrict__ fc_b,
    float* __restrict__ d_out, int out_size)
{
    __shared__ __align__(16) float sh[H_DIM];   // h[s] staged for dot products
    __shared__ float ssum[16];                  // per-row dot sums
    __shared__ float sgin[16];                  // input gates (warp-0 private)
    __shared__ int   stags[T_STEPS];

    const int tid    = threadIdx.x;
    const int base   = blockIdx.x * 4;           // first hidden unit owned
    const int rid    = tid >> 4;                 // 0..15: gate row id
    const int lane16 = tid & 15;
    const int g      = rid >> 2;                 // gate: 0=i 1=f 2=g 3=o
    const int ul     = rid & 3;                  // unit within CTA
    const int row    = g * H_DIM + base + ul;    // global gate row

    for (int i = tid; i < T_STEPS; i += 256) stags[i] = tags[i];
    float cval = 0.f, hval = 0.f;
    if (tid < 4) cval = c0[base + tid];
    __syncthreads();

    // Preload step-0 weights: thread handles k = lane16*4 + 64*m, m=0..7
    float4 wc[8], wn[8];
    {
        const float4* p = (const float4*)(W_hh + ((size_t)stags[0] * G_DIM + row) * H_DIM + lane16 * 4);
        #pragma unroll
        for (int m = 0; m < 8; m++) wc[m] = __ldg(&p[m * 16]);
    }

    const float2* ghp = (const float2*)g_h;

    for (int s = 0; s < T_STEPS; s++) {
        // 1. Prefetch next step's weights (tags known upfront -> hides L2 latency)
        {
            int sn = (s + 1 < T_STEPS) ? s + 1 : s;
            const float4* p = (const float4*)(W_hh + ((size_t)stags[sn] * G_DIM + row) * H_DIM + lane16 * 4);
            #pragma unroll
            for (int m = 0; m < 8; m++) wn[m] = __ldg(&p[m * 16]);
        }
        // 2. Prefetch this step's input gate values (warp 0, lanes 0-15)
        if (tid < 16)
            sgin[tid] = __ldg(&g_gates[s * G_DIM + (tid >> 2) * H_DIM + base + (tid & 3)]);

        // 3. Poll h[s] with a 2-deep rotated load pipeline: the check is on a
        //    load that already landed, so the loop period is ~10-30 cyc instead
        //    of a full L2 round trip. Detection ~ (one-way + RT) after the store.
        {
            const float2* p = &ghp[s * (H_DIM / 2) + tid];
            float2 a = ld_vol_f2(p);
            if (is_snan(a.x) || is_snan(a.y)) {
                float2 b = ld_vol_f2(p);
                while (is_snan(a.x) || is_snan(a.y)) {
                    a = b;
                    b = ld_vol_f2(p);
                }
            }
            sh[2 * tid]     = a.x;
            sh[2 * tid + 1] = a.y;
        }
        __syncthreads();

        // 4. 16-lane dot product, 4 accumulators (short FMA chains)
        const float4* sh4 = (const float4*)sh;
        float a0 = 0.f, a1 = 0.f, a2 = 0.f, a3 = 0.f;
        #pragma unroll
        for (int m = 0; m < 8; m += 4) {
            float4 h0v = sh4[lane16 + (m + 0) * 16];
            float4 h1v = sh4[lane16 + (m + 1) * 16];
            float4 h2v = sh4[lane16 + (m + 2) * 16];
            float4 h3v = sh4[lane16 + (m + 3) * 16];
            a0 += wc[m+0].x * h0v.x + wc[m+0].y * h0v.y + wc[m+0].z * h0v.z + wc[m+0].w * h0v.w;
            a1 += wc[m+1].x * h1v.x + wc[m+1].y * h1v.y + wc[m+1].z * h1v.z + wc[m+1].w * h1v.w;
            a2 += wc[m+2].x * h2v.x + wc[m+2].y * h2v.y + wc[m+2].z * h2v.z + wc[m+2].w * h2v.w;
            a3 += wc[m+3].x * h3v.x + wc[m+3].y * h3v.y + wc[m+3].z * h3v.z + wc[m+3].w * h3v.w;
        }
        float acc = (a0 + a1) + (a2 + a3);
        #pragma unroll
        for (int off = 8; off; off >>= 1)
            acc += __shfl_down_sync(0xffffffffu, acc, off, 16);
        if (lane16 == 0) ssum[rid] = acc;
        __syncthreads();

        // 5. Nonlinearity in lanes 0-3: four INDEPENDENT MUFU chains per lane
        //    (HW pipelines them), no cross-lane traffic.
        if (tid < 4) {
            float zi = sgin[0  + tid] + ssum[0  + tid];
            float zf = sgin[4  + tid] + ssum[4  + tid];
            float zg = sgin[8  + tid] + ssum[8  + tid];
            float zo = sgin[12 + tid] + ssum[12 + tid];
            float ei = __expf(-zi), ef = __expf(-zf);
            float eg = __expf(-2.f * zg), eo = __expf(-zo);
            float iv = __fdividef(1.f, 1.f + ei);
            float fv = __fdividef(1.f, 1.f + ef);
            float gv = __fdividef(1.f - eg, 1.f + eg);
            float ov = __fdividef(1.f, 1.f + eo);
            cval = fv * cval + iv * gv;
            float e2 = __expf(-2.f * cval);
            hval = ov * __fdividef(1.f - e2, 1.f + e2);
            st_vol_f(&g_h[(s + 1) * H_DIM + base + tid], hval);   // the "flag"
        }
        #pragma unroll
        for (int m = 0; m < 8; m++) wc[m] = wn[m];
    }

    // Output layout: [out(1), h(512), c(512)] — h/c only if harness sized it so
    if (tid < 4 && out_size >= 1 + 2 * H_DIM) {
        d_out[1 + base + tid]         = hval;
        d_out[1 + H_DIM + base + tid] = cval;
    }

    // Block 0: out = sigmoid(h_T . fc_w + fc_b)   (fused out_kernel)
    if (blockIdx.x == 0) {
        const float2* hp = (const float2*)(g_h + T_STEPS * H_DIM);
        float2 hv = ld_vol_f2(&hp[tid]);
        while (is_snan(hv.x) || is_snan(hv.y)) hv = ld_vol_f2(&hp[tid]);
        float v = hv.x * __ldg(&fc_w[2 * tid]) + hv.y * __ldg(&fc_w[2 * tid + 1]);
        #pragma unroll
        for (int off = 16; off; off >>= 1) v += __shfl_down_sync(0xffffffffu, v, off);
        if ((tid & 31) == 0) ssum[tid >> 5] = v;
        __syncthreads();
        if (tid < 8) {
            v = ssum[tid];
            #pragma unroll
            for (int off = 4; off; off >>= 1) v += __shfl_down_sync(0xffu, v, off, 8);
            if (tid == 0) d_out[0] = __fdividef(1.f, 1.f + __expf(-(v + fc_b[0])));
        }
    }
}

// ---------------------------------------------------------------------------
// Launch. Input order: x, tags, h0, c0, emb, W_ih, W_hh, b_ih, b_hh, fc_w, fc_b.
// ---------------------------------------------------------------------------
extern "C" void kernel_launch(void* const* d_in, const int* in_sizes, int n_in,
                              void* d_out, int out_size)
{
    const int*   x32  = (const int*)  d_in[0];   // int32 OR int64 (device probe)
    const int*   tags = (const int*)  d_in[1];
    const float* h0   = (const float*)d_in[2];
    const float* c0   = (const float*)d_in[3];
    const float* emb  = (const float*)d_in[4];
    const float* W_ih = (const float*)d_in[5];
    const float* W_hh = (const float*)d_in[6];
    const float* b_ih = (const float*)d_in[7];
    const float* b_hh = (const float*)d_in[8];
    const float* fc_w = (const float*)d_in[9];
    const float* fc_b = (const float*)d_in[10];
    float* out = (float*)d_out;

    init_kernel<<<((T_STEPS + 1) * H_DIM + 511) / 512, 512>>>(h0);
    gates_kernel<<<GATE_BLOCKS, 256>>>(x32, tags, emb, W_ih, b_ih, b_hh);
    lstm_kernel<<<NCTA, 256>>>(tags, W_hh, c0, fc_w, fc_b, out, out_size);
}

// round 8
// speedup vs baseline: 1.2525x; 1.1256x over previous
#include <cuda_runtime.h>
#include <cstdint>

#define T_STEPS 300
#define E_DIM   300
#define H_DIM   512
#define G_DIM   2048   // 4*H
#define N_EXP   13
#define V_SIZE  400000
#define NCTA    128    // recurrent CTAs; 4 hidden units each
#define ROWS_PER_BLK 32
#define SENTINEL 2.0f  // |h| <= 1.0 always, so 2.0f is unreachable

// Scratch (device globals: no allocation allowed)
__device__ float g_gates[T_STEPS * G_DIM];                      // input gates (+biases)
__device__ __align__(16) float g_h[(T_STEPS + 1) * H_DIM];      // step-indexed hidden states

// ---------------------------------------------------------------------------
// Volatile global access helpers (compiler cannot hoist/elide these)
// ---------------------------------------------------------------------------
__device__ __forceinline__ float2 ld_vol_f2(const float2* p) {
    float2 v;
    asm volatile("ld.volatile.global.v2.f32 {%0,%1}, [%2];"
                 : "=f"(v.x), "=f"(v.y) : "l"(p));
    return v;
}
__device__ __forceinline__ void st_vol_f(float* p, float v) {
    asm volatile("st.volatile.global.f32 [%0], %1;" :: "l"(p), "f"(v));
}

// ---------------------------------------------------------------------------
// Kernel 1: re-initialize h buffers each replay. g_h[0] = h0, rest = sentinel.
// ---------------------------------------------------------------------------
__global__ void init_kernel(const float* __restrict__ h0) {
    int idx = blockIdx.x * blockDim.x + threadIdx.x;
    if (idx < (T_STEPS + 1) * H_DIM)
        g_h[idx] = (idx < H_DIM) ? h0[idx] : SENTINEL;
}

// ---------------------------------------------------------------------------
// x-buffer layout probe: reference declares int64 but JAX w/o x64 yields int32.
// If truly int64, every odd 32-bit word is 0 (all ids in [0, 4e5)).
// ---------------------------------------------------------------------------
__device__ __forceinline__ bool probe_is_i64(const int* __restrict__ x32) {
    bool all_zero = true;
    #pragma unroll
    for (int i = 1; i < 64; i += 2) all_zero &= (x32[i] == 0);
    return all_zero;
}

__device__ __forceinline__ int load_token(const int* __restrict__ x32, int t, bool i64) {
    int v = i64 ? x32[2 * t] : x32[t];
    return (v < 0) ? 0 : (v >= V_SIZE ? V_SIZE - 1 : v);   // defensive clamp
}

// ---------------------------------------------------------------------------
// Kernel 2: input gates. Block = (expert, 32-row chunk). W_ih chunk in SMEM
// once; loop timesteps routed to this expert.
// gates[t][row] = dot(emb[x[t]], W_ih[e][row]) + b_ih[e][row] + b_hh[e][row]
// ---------------------------------------------------------------------------
__global__ void __launch_bounds__(256) gates_kernel(
    const int* __restrict__ x32, const int* __restrict__ tags,
    const float* __restrict__ emb, const float* __restrict__ W_ih,
    const float* __restrict__ b_ih, const float* __restrict__ b_hh)
{
    __shared__ float sw[ROWS_PER_BLK * E_DIM];   // 37.5 KB
    __shared__ float sx[E_DIM];
    __shared__ float sb[ROWS_PER_BLK];
    __shared__ int   stags[T_STEPS];
    __shared__ int   s_i64;

    const int e     = blockIdx.x / (G_DIM / ROWS_PER_BLK);
    const int chunk = blockIdx.x % (G_DIM / ROWS_PER_BLK);
    const int row0  = chunk * ROWS_PER_BLK;
    const int tid   = threadIdx.x;

    const float* wsrc = W_ih + ((size_t)e * G_DIM + row0) * E_DIM;
    for (int i = tid; i < ROWS_PER_BLK * E_DIM; i += 256) sw[i] = wsrc[i];
    if (tid < ROWS_PER_BLK)
        sb[tid] = b_ih[e * G_DIM + row0 + tid] + b_hh[e * G_DIM + row0 + tid];
    for (int i = tid; i < T_STEPS; i += 256) stags[i] = tags[i];
    if (tid == 0) s_i64 = probe_is_i64(x32) ? 1 : 0;
    __syncthreads();

    const bool i64  = (s_i64 != 0);
    const int row   = tid >> 3;   // 0..31
    const int lane8 = tid & 7;

    for (int t = 0; t < T_STEPS; t++) {
        if (stags[t] != e) continue;                 // uniform branch (smem)
        const float* xe = emb + (size_t)load_token(x32, t, i64) * E_DIM;
        for (int i = tid; i < E_DIM; i += 256) sx[i] = xe[i];
        __syncthreads();
        float acc = 0.f;
        for (int k = lane8; k < E_DIM; k += 8)
            acc += sw[row * E_DIM + k] * sx[k];
        #pragma unroll
        for (int off = 4; off; off >>= 1)
            acc += __shfl_down_sync(0xffffffffu, acc, off, 8);
        if (lane8 == 0)
            g_gates[t * G_DIM + row0 + row] = acc + sb[row];
        __syncthreads();
    }
}

// ---------------------------------------------------------------------------
// Kernel 3: persistent recurrent LSTM. 128 CTAs x 256 threads.
// CTA c owns hidden units [4c, 4c+4); 16 gate rows per step.
// Sync: sentinel polling (2.0f) on step-indexed g_h via volatile ld/st.
// Only change vs the 848us baseline: step-5 nonlinearity uses overflow-safe
// MUFU math (EX2+RCP) instead of precise tanhf/expf slow paths.
// ---------------------------------------------------------------------------
__global__ void __launch_bounds__(256, 1) lstm_kernel(
    const int* __restrict__ tags, const float* __restrict__ W_hh,
    const float* __restrict__ c0, float* __restrict__ d_out, int out_size)
{
    __shared__ float sh[H_DIM];       // h[s] staged for dot products
    __shared__ float ssum[16];        // per-row partial sums
    __shared__ float sgin[2][16];     // input gates (double-buffered)
    __shared__ int   stags[T_STEPS];

    const int tid    = threadIdx.x;
    const int base   = blockIdx.x * 4;        // first hidden unit owned
    const int rid    = tid >> 4;              // 0..15: gate row id
    const int lane16 = tid & 15;
    const int g      = rid >> 2;              // gate: 0=i 1=f 2=g 3=o
    const int ul     = rid & 3;               // unit within CTA
    const int row    = g * H_DIM + base + ul; // global gate row

    for (int i = tid; i < T_STEPS; i += 256) stags[i] = tags[i];
    float cval = 0.f, hval = 0.f;
    if (tid < 4) cval = c0[base + tid];
    __syncthreads();

    // Preload step-0 weights: thread handles k = lane16*4 + 64*m
    float4 wc[8], wn[8];
    {
        const float4* p = (const float4*)(W_hh + ((size_t)stags[0] * G_DIM + row) * H_DIM + lane16 * 4);
        #pragma unroll
        for (int m = 0; m < 8; m++) wc[m] = __ldg(&p[m * 16]);
    }

    const float2* ghp = (const float2*)g_h;

    for (int s = 0; s < T_STEPS; s++) {
        // 1. Prefetch next step's weights (tags known upfront -> hides L2 latency)
        {
            int sn = (s + 1 < T_STEPS) ? s + 1 : s;
            const float4* p = (const float4*)(W_hh + ((size_t)stags[sn] * G_DIM + row) * H_DIM + lane16 * 4);
            #pragma unroll
            for (int m = 0; m < 8; m++) wn[m] = __ldg(&p[m * 16]);
        }
        // 2. Prefetch this step's input gates (16 values per CTA)
        float gin = 0.f;
        if (tid < 16)
            gin = __ldg(&g_gates[s * G_DIM + (tid >> 2) * H_DIM + base + (tid & 3)]);

        // 3. Poll h[s]: each thread owns 2 floats; SENTINEL = not yet produced
        float2 hv = ld_vol_f2(&ghp[s * (H_DIM / 2) + tid]);
        while (hv.x == SENTINEL || hv.y == SENTINEL)
            hv = ld_vol_f2(&ghp[s * (H_DIM / 2) + tid]);
        sh[2 * tid]     = hv.x;
        sh[2 * tid + 1] = hv.y;
        if (tid < 16) sgin[s & 1][tid] = gin;
        __syncthreads();

        // 4. 16-lane dot product (conflict-free float4 smem reads)
        const float4* sh4 = (const float4*)sh;
        float acc = 0.f;
        #pragma unroll
        for (int m = 0; m < 8; m++) {
            float4 h4 = sh4[lane16 + m * 16];
            acc += wc[m].x * h4.x + wc[m].y * h4.y + wc[m].z * h4.z + wc[m].w * h4.w;
        }
        #pragma unroll
        for (int off = 8; off; off >>= 1)
            acc += __shfl_down_sync(0xffffffffu, acc, off, 16);
        if (lane16 == 0) ssum[rid] = acc;
        __syncthreads();

        // 5. Elementwise LSTM update (MUFU fast math, overflow-safe):
        //    sigmoid(z) = 1/(1+exp(-z))  [inf-safe: exp->inf gives 0]
        //    tanh(z)    = copysign((1-e)/(1+e), z), e = exp(-2|z|) <= 1
        if (tid < 4) {
            const float* sg = sgin[s & 1];
            float zi = sg[0 * 4 + tid] + ssum[0 * 4 + tid];
            float zf = sg[1 * 4 + tid] + ssum[1 * 4 + tid];
            float zg = sg[2 * 4 + tid] + ssum[2 * 4 + tid];
            float zo = sg[3 * 4 + tid] + ssum[3 * 4 + tid];
            float iv = __fdividef(1.f, 1.f + __expf(-zi));
            float fv = __fdividef(1.f, 1.f + __expf(-zf));
            float eg = __expf(-2.f * fabsf(zg));
            float gv = copysignf(__fdividef(1.f - eg, 1.f + eg), zg);
            float ov = __fdividef(1.f, 1.f + __expf(-zo));
            cval = fv * cval + iv * gv;
            float ec = __expf(-2.f * fabsf(cval));
            hval = ov * copysignf(__fdividef(1.f - ec, 1.f + ec), cval);
            st_vol_f(&g_h[(s + 1) * H_DIM + base + tid], hval);   // the "flag"
        }
        #pragma unroll
        for (int m = 0; m < 8; m++) wc[m] = wn[m];
    }

    // Output layout: [out(1), h(512), c(512)] — only if harness sized it so
    if (tid < 4 && out_size >= 1 + 2 * H_DIM) {
        d_out[1 + base + tid]          = hval;
        d_out[1 + H_DIM + base + tid]  = cval;
    }
}

// ---------------------------------------------------------------------------
// Kernel 4: out = sigmoid(h_T . fc_w + fc_b)   (O = 1)
// ---------------------------------------------------------------------------
__global__ void out_kernel(const float* __restrict__ fc_w,
                           const float* __restrict__ fc_b,
                           float* __restrict__ d_out)
{
    __shared__ float red[16];
    int tid = threadIdx.x;   // 512 threads
    float v = g_h[T_STEPS * H_DIM + tid] * fc_w[tid];
    #pragma unroll
    for (int off = 16; off; off >>= 1) v += __shfl_down_sync(0xffffffffu, v, off);
    if ((tid & 31) == 0) red[tid >> 5] = v;
    __syncthreads();
    if (tid < 16) {
        v = red[tid];
        #pragma unroll
        for (int off = 8; off; off >>= 1) v += __shfl_down_sync(0xffffu, v, off, 16);
        if (tid == 0) d_out[0] = 1.f / (1.f + expf(-(v + fc_b[0])));
    }
}

// ---------------------------------------------------------------------------
// Launch. Input order: x, tags, h0, c0, emb, W_ih, W_hh, b_ih, b_hh, fc_w, fc_b.
// ---------------------------------------------------------------------------
extern "C" void kernel_launch(void* const* d_in, const int* in_sizes, int n_in,
                              void* d_out, int out_size)
{
    const int*   x32  = (const int*)  d_in[0];   // int32 OR int64 (device probe)
    const int*   tags = (const int*)  d_in[1];
    const float* h0   = (const float*)d_in[2];
    const float* c0   = (const float*)d_in[3];
    const float* emb  = (const float*)d_in[4];
    const float* W_ih = (const float*)d_in[5];
    const float* W_hh = (const float*)d_in[6];
    const float* b_ih = (const float*)d_in[7];
    const float* b_hh = (const float*)d_in[8];
    const float* fc_w = (const float*)d_in[9];
    const float* fc_b = (const float*)d_in[10];
    float* out = (float*)d_out;

    init_kernel<<<((T_STEPS + 1) * H_DIM + 511) / 512, 512>>>(h0);
    gates_kernel<<<N_EXP * (G_DIM / ROWS_PER_BLK), 256>>>(x32, tags, emb, W_ih, b_ih, b_hh);
    lstm_kernel<<<NCTA, 256>>>(tags, W_hh, c0, out, out_size);
    out_kernel<<<1, H_DIM>>>(fc_w, fc_b, out);
}

// round 9
// speedup vs baseline: 1.8807x; 1.5015x over previous
#include <cuda_runtime.h>
#include <cstdint>

#define T_STEPS 300
#define E_DIM   300
#define H_DIM   512
#define G_DIM   2048   // 4*H
#define N_EXP   13
#define V_SIZE  400000
#define NCTA    64     // recurrent CTAs; 8 hidden units each
#define UNITS   8
#define NTHR    512
#define DEPTH   8      // mailbox ring depth (power of 2)
#define ROWS_PER_BLK 32
#define SENTINEL 2.0f  // |h| <= 1 always; h0 = 0 in this problem

// Scratch (device globals: no allocation allowed)
__device__ float g_gates[T_STEPS * G_DIM];                       // input gates (+biases)
__device__ __align__(16) float g_box[NCTA * DEPTH * H_DIM];      // private mailboxes, 1 MB

// ---------------------------------------------------------------------------
// Volatile global access helpers (compiler cannot hoist/elide these)
// ---------------------------------------------------------------------------
__device__ __forceinline__ float ld_vol_f(const float* p) {
    float v;
    asm volatile("ld.volatile.global.f32 %0, [%1];" : "=f"(v) : "l"(p));
    return v;
}
__device__ __forceinline__ float4 ld_vol_f4(const float4* p) {
    float4 v;
    asm volatile("ld.volatile.global.v4.f32 {%0,%1,%2,%3}, [%4];"
                 : "=f"(v.x), "=f"(v.y), "=f"(v.z), "=f"(v.w) : "l"(p));
    return v;
}
__device__ __forceinline__ void st_vol_f4(float4* p, float4 v) {
    asm volatile("st.volatile.global.v4.f32 [%0], {%1,%2,%3,%4};"
                 :: "l"(p), "f"(v.x), "f"(v.y), "f"(v.z), "f"(v.w));
}

// ---------------------------------------------------------------------------
// Kernel 1: re-init mailboxes each replay. Depth 0 = h0 (step 0's input);
// all other depths = sentinel.
// ---------------------------------------------------------------------------
__global__ void init_kernel(const float* __restrict__ h0) {
    int idx = blockIdx.x * blockDim.x + threadIdx.x;
    if (idx < NCTA * DEPTH * H_DIM) {
        int k = idx & (H_DIM - 1);
        int d = (idx >> 9) & (DEPTH - 1);
        g_box[idx] = (d == 0) ? h0[k] : SENTINEL;
    }
}

// ---------------------------------------------------------------------------
// x-buffer probe: reference declares int64 but JAX w/o x64 yields int32.
// ---------------------------------------------------------------------------
__device__ __forceinline__ bool probe_is_i64(const int* __restrict__ x32) {
    bool all_zero = true;
    #pragma unroll
    for (int i = 1; i < 64; i += 2) all_zero &= (x32[i] == 0);
    return all_zero;
}
__device__ __forceinline__ int load_token(const int* __restrict__ x32, int t, bool i64) {
    int v = i64 ? x32[2 * t] : x32[t];
    return (v < 0) ? 0 : (v >= V_SIZE ? V_SIZE - 1 : v);
}

// ---------------------------------------------------------------------------
// Kernel 2: input gates (unchanged; proven). Stream-ordered before lstm, so
// lstm reads g_gates with plain __ldg — no sentinels needed.
// ---------------------------------------------------------------------------
__global__ void __launch_bounds__(256) gates_kernel(
    const int* __restrict__ x32, const int* __restrict__ tags,
    const float* __restrict__ emb, const float* __restrict__ W_ih,
    const float* __restrict__ b_ih, const float* __restrict__ b_hh)
{
    __shared__ float sw[ROWS_PER_BLK * E_DIM];   // 37.5 KB
    __shared__ float sx[E_DIM];
    __shared__ float sb[ROWS_PER_BLK];
    __shared__ int   stags[T_STEPS];
    __shared__ int   s_i64;

    const int e     = blockIdx.x / (G_DIM / ROWS_PER_BLK);
    const int chunk = blockIdx.x % (G_DIM / ROWS_PER_BLK);
    const int row0  = chunk * ROWS_PER_BLK;
    const int tid   = threadIdx.x;

    const float* wsrc = W_ih + ((size_t)e * G_DIM + row0) * E_DIM;
    for (int i = tid; i < ROWS_PER_BLK * E_DIM; i += 256) sw[i] = wsrc[i];
    if (tid < ROWS_PER_BLK)
        sb[tid] = b_ih[e * G_DIM + row0 + tid] + b_hh[e * G_DIM + row0 + tid];
    for (int i = tid; i < T_STEPS; i += 256) stags[i] = tags[i];
    if (tid == 0) s_i64 = probe_is_i64(x32) ? 1 : 0;
    __syncthreads();

    const bool i64  = (s_i64 != 0);
    const int row   = tid >> 3;   // 0..31
    const int lane8 = tid & 7;

    for (int t = 0; t < T_STEPS; t++) {
        if (stags[t] != e) continue;                 // uniform branch (smem)
        const float* xe = emb + (size_t)load_token(x32, t, i64) * E_DIM;
        for (int i = tid; i < E_DIM; i += 256) sx[i] = xe[i];
        __syncthreads();
        float acc = 0.f;
        for (int k = lane8; k < E_DIM; k += 8)
            acc += sw[row * E_DIM + k] * sx[k];
        #pragma unroll
        for (int off = 4; off; off >>= 1)
            acc += __shfl_down_sync(0xffffffffu, acc, off, 8);
        if (lane8 == 0)
            g_gates[t * G_DIM + row0 + row] = acc + sb[row];
        __syncthreads();
    }
}

// ---------------------------------------------------------------------------
// Kernel 3: recurrent LSTM, 64 CTAs x 512 threads, private-mailbox sync.
// CTA b owns units [8b, 8b+8) -> 32 gate rows; 16 threads per row.
// Producers BROADCAST their h-slice into every consumer's private mailbox;
// each consumer polls only its own 2KB region (no hot-sector storm).
// ---------------------------------------------------------------------------
__global__ void __launch_bounds__(NTHR, 1) lstm_kernel(
    const int* __restrict__ tags, const float* __restrict__ W_hh,
    const float* __restrict__ c0,
    const float* __restrict__ fc_w, const float* __restrict__ fc_b,
    float* __restrict__ d_out, int out_size)
{
    __shared__ __align__(16) float sh[H_DIM];   // h[s] staged
    __shared__ float ssum[32];                  // per-row dot sums
    __shared__ float sgin[32];                  // input gates for this step
    __shared__ int   stags[T_STEPS];

    const int tid    = threadIdx.x;
    const int base   = blockIdx.x * UNITS;      // first hidden unit owned
    const int rid    = tid >> 4;                // 0..31: gate row id
    const int lane16 = tid & 15;
    const int g      = rid >> 3;                // gate: 0=i 1=f 2=g 3=o
    const int u      = rid & 7;                 // unit within CTA
    const int row    = g * H_DIM + base + u;    // global gate row

    for (int i = tid; i < T_STEPS; i += NTHR) stags[i] = tags[i];
    float cval = 0.f, hval = 0.f;
    if (tid < UNITS) cval = c0[base + tid];
    __syncthreads();

    // Preload step-0 weights: thread covers k = lane16*4 + 64*m, m=0..7
    float4 wc[8], wn[8];
    {
        const float4* p = (const float4*)(W_hh + ((size_t)stags[0] * G_DIM + row) * H_DIM) + lane16;
        #pragma unroll
        for (int m = 0; m < 8; m++) wc[m] = __ldg(p + m * 16);
    }

    float4* const mybox = (float4*)(g_box + (size_t)blockIdx.x * DEPTH * H_DIM);
    const float4 sent4 = make_float4(SENTINEL, SENTINEL, SENTINEL, SENTINEL);

    for (int s = 0; s < T_STEPS; s++) {
        // 1. Prefetch next step's weights (tag known -> hides L2 latency)
        {
            int sn = (s + 1 < T_STEPS) ? s + 1 : s;
            const float4* p = (const float4*)(W_hh + ((size_t)stags[sn] * G_DIM + row) * H_DIM) + lane16;
            #pragma unroll
            for (int m = 0; m < 8; m++) wn[m] = __ldg(p + m * 16);
        }
        // 2. Input gates for this step (warp 0; consumed after bar-2 by tid<8)
        if (tid < 32)
            sgin[tid] = __ldg(&g_gates[s * G_DIM + (tid >> 3) * H_DIM + base + (tid & 7)]);

        // 3. Poll OWN mailbox (warps 4-7; private region -> contention-free).
        //    2-deep rotated pipeline: check lands on an already-completed load.
        if ((tid >> 7) == 1) {
            const int i = tid & 127;                       // float4 index 0..127
            const float4* p = mybox + (s & (DEPTH - 1)) * (H_DIM / 4) + i;
            float4 a = ld_vol_f4(p);
            if (a.x == SENTINEL || a.y == SENTINEL || a.z == SENTINEL || a.w == SENTINEL) {
                float4 b2 = ld_vol_f4(p);
                while (a.x == SENTINEL || a.y == SENTINEL || a.z == SENTINEL || a.w == SENTINEL) {
                    a = b2;
                    b2 = ld_vol_f4(p);
                }
            }
            ((float4*)sh)[i] = a;
            st_vol_f4((float4*)p, sent4);                  // reset for reuse at s+8
        }
        __syncthreads();

        // 4. Dot: 16 lanes per row, 8 float4-FMA groups each (conflict-free)
        const float4* sh4 = (const float4*)sh;
        float a0 = 0.f, a1 = 0.f;
        #pragma unroll
        for (int m = 0; m < 8; m += 2) {
            float4 hA = sh4[lane16 + (m + 0) * 16];
            float4 hB = sh4[lane16 + (m + 1) * 16];
            a0 += wc[m+0].x * hA.x + wc[m+0].y * hA.y + wc[m+0].z * hA.z + wc[m+0].w * hA.w;
            a1 += wc[m+1].x * hB.x + wc[m+1].y * hB.y + wc[m+1].z * hB.z + wc[m+1].w * hB.w;
        }
        float acc = a0 + a1;
        #pragma unroll
        for (int off = 8; off; off >>= 1)
            acc += __shfl_down_sync(0xffffffffu, acc, off, 16);
        if (lane16 == 0) ssum[rid] = acc;
        __syncthreads();

        // 5. Warp 0: nonlinearity (lanes 0-7, overflow-safe MUFU) + BROADCAST
        //    h[s+1] into every consumer's private mailbox.
        if (tid < 32) {
            if (tid < 8) {
                float zi = sgin[tid]      + ssum[tid];
                float zf = sgin[8  + tid] + ssum[8  + tid];
                float zg = sgin[16 + tid] + ssum[16 + tid];
                float zo = sgin[24 + tid] + ssum[24 + tid];
                float iv = __fdividef(1.f, 1.f + __expf(-zi));
                float fv = __fdividef(1.f, 1.f + __expf(-zf));
                float eg = __expf(-2.f * fabsf(zg));
                float gv = copysignf(__fdividef(1.f - eg, 1.f + eg), zg);
                float ov = __fdividef(1.f, 1.f + __expf(-zo));
                cval = fv * cval + iv * gv;
                float ec = __expf(-2.f * fabsf(cval));
                hval = ov * copysignf(__fdividef(1.f - ec, 1.f + ec), cval);
            }
            // collect the 8 fresh h values into every lane of warp 0
            float h0_ = __shfl_sync(0xffffffffu, hval, 0);
            float h1_ = __shfl_sync(0xffffffffu, hval, 1);
            float h2_ = __shfl_sync(0xffffffffu, hval, 2);
            float h3_ = __shfl_sync(0xffffffffu, hval, 3);
            float h4_ = __shfl_sync(0xffffffffu, hval, 4);
            float h5_ = __shfl_sync(0xffffffffu, hval, 5);
            float h6_ = __shfl_sync(0xffffffffu, hval, 6);
            float h7_ = __shfl_sync(0xffffffffu, hval, 7);
            float4 lo = make_float4(h0_, h1_, h2_, h3_);
            float4 hi = make_float4(h4_, h5_, h6_, h7_);
            const int b = (s + 1) & (DEPTH - 1);
            #pragma unroll
            for (int cc = 0; cc < 2; cc++) {
                int cons = tid + cc * 32;                  // 2 consumers per lane
                float4* dst = (float4*)(g_box + ((size_t)cons * DEPTH + b) * H_DIM + base);
                st_vol_f4(dst,     lo);
                st_vol_f4(dst + 1, hi);
            }
        }
        #pragma unroll
        for (int m = 0; m < 8; m++) wc[m] = wn[m];
    }

    // Output layout: [out(1), h(512), c(512)] — h/c only if harness sized it so
    if (tid < UNITS && out_size >= 1 + 2 * H_DIM) {
        d_out[1 + base + tid]         = hval;
        d_out[1 + H_DIM + base + tid] = cval;
    }

    // Block 0: out = sigmoid(h_T . fc_w + fc_b). h_T lives (unconsumed) in
    // block 0's mailbox buffer (T_STEPS & 7).
    if (blockIdx.x == 0) {
        const float* hp = g_box + (size_t)(T_STEPS & (DEPTH - 1)) * H_DIM;  // cons 0
        float v = ld_vol_f(&hp[tid]);
        while (v == SENTINEL) v = ld_vol_f(&hp[tid]);
        v *= __ldg(&fc_w[tid]);
        #pragma unroll
        for (int off = 16; off; off >>= 1) v += __shfl_down_sync(0xffffffffu, v, off);
        if ((tid & 31) == 0) ssum[tid >> 5] = v;          // 16 warps
        __syncthreads();
        if (tid < 16) {
            v = ssum[tid];
            #pragma unroll
            for (int off = 8; off; off >>= 1) v += __shfl_down_sync(0xffffu, v, off, 16);
            if (tid == 0) d_out[0] = __fdividef(1.f, 1.f + __expf(-(v + fc_b[0])));
        }
    }
}

// ---------------------------------------------------------------------------
// Launch. Input order: x, tags, h0, c0, emb, W_ih, W_hh, b_ih, b_hh, fc_w, fc_b.
// ---------------------------------------------------------------------------
extern "C" void kernel_launch(void* const* d_in, const int* in_sizes, int n_in,
                              void* d_out, int out_size)
{
    const int*   x32  = (const int*)  d_in[0];   // int32 OR int64 (device probe)
    const int*   tags = (const int*)  d_in[1];
    const float* h0   = (const float*)d_in[2];
    const float* c0   = (const float*)d_in[3];
    const float* emb  = (const float*)d_in[4];
    const float* W_ih = (const float*)d_in[5];
    const float* W_hh = (const float*)d_in[6];
    const float* b_ih = (const float*)d_in[7];
    const float* b_hh = (const float*)d_in[8];
    const float* fc_w = (const float*)d_in[9];
    const float* fc_b = (const float*)d_in[10];
    float* out = (float*)d_out;

    init_kernel<<<(NCTA * DEPTH * H_DIM + 511) / 512, 512>>>(h0);
    gates_kernel<<<N_EXP * (G_DIM / ROWS_PER_BLK), 256>>>(x32, tags, emb, W_ih, b_ih, b_hh);
    lstm_kernel<<<NCTA, NTHR>>>(tags, W_hh, c0, fc_w, fc_b, out, out_size);
}